// round 15
// baseline (speedup 1.0000x reference)
#include <cuda_runtime.h>
#include <cuda_fp16.h>
#include <cstdint>

#define B_ 16
#define C_ 512
#define N_ 4096   // H*W
#define W_ 64

// ---------------- scratch (__device__ globals: allocation-free rule) --------
__device__ __half g_qh[(size_t)B_ * C_ * N_];   // 67 MB each
__device__ __half g_ql[(size_t)B_ * C_ * N_];
__device__ __half g_kh[(size_t)B_ * C_ * N_];
__device__ __half g_kl[(size_t)B_ * C_ * N_];
__device__ __half g_ah[(size_t)B_ * C_ * C_];   // attention (fp16)
__device__ float  g_energy[(size_t)B_ * C_ * C_];

// ---------------- plain-target PTX helpers ----------------------------------
__device__ __forceinline__ uint32_t smem_u32(const void* p) {
    uint32_t a;
    asm("{ .reg .u64 t; cvta.to.shared.u64 t, %1; cvt.u32.u64 %0, t; }" : "=r"(a) : "l"(p));
    return a;
}
__device__ __forceinline__ void ldsm4(uint32_t* r, uint32_t addr) {
    asm volatile("ldmatrix.sync.aligned.m8n8.x4.shared.b16 {%0,%1,%2,%3}, [%4];"
                 : "=r"(r[0]), "=r"(r[1]), "=r"(r[2]), "=r"(r[3]) : "r"(addr));
}
__device__ __forceinline__ void ldsm4t(uint32_t* r, uint32_t addr) {
    asm volatile("ldmatrix.sync.aligned.m8n8.x4.trans.shared.b16 {%0,%1,%2,%3}, [%4];"
                 : "=r"(r[0]), "=r"(r[1]), "=r"(r[2]), "=r"(r[3]) : "r"(addr));
}
__device__ __forceinline__ void mma16816(float* d, const uint32_t* a, const uint32_t* b) {
    asm volatile(
        "mma.sync.aligned.m16n8k16.row.col.f32.f16.f16.f32 "
        "{%0,%1,%2,%3}, {%4,%5,%6,%7}, {%8,%9}, {%0,%1,%2,%3};"
        : "+f"(d[0]), "+f"(d[1]), "+f"(d[2]), "+f"(d[3])
        : "r"(a[0]), "r"(a[1]), "r"(a[2]), "r"(a[3]), "r"(b[0]), "r"(b[1]));
}
#define CP_ASYNC16(s, g) \
    asm volatile("cp.async.cg.shared.global [%0], [%1], 16;" :: "r"(s), "l"(g))
#define CP_COMMIT()  asm volatile("cp.async.commit_group;" ::: "memory")
#define CP_WAIT1()   asm volatile("cp.async.wait_group 1;" ::: "memory")

// Swizzled byte offsets inside an 8 KB tile.
// A-type tile: 128 rows x 32 halves (64 B/row); chunk = 16 B.
__device__ __forceinline__ uint32_t offA(int row, int ch) {
    return row * 64 + ((ch ^ ((row >> 1) & 3)) * 16);
}
// B-type tile (n-major): 32 rows x 128 halves (256 B/row).
__device__ __forceinline__ uint32_t offB(int krow, int ch) {
    return krow * 256 + ((ch ^ (krow & 7)) * 16);
}

static constexpr int STAGES = 3;
// gemm1: 4 tiles x 8 KB; gemm2: 2 tiles x 8 KB (A + Bh only)
static constexpr int STAGE1_SZ = 32768;
static constexpr int SMEM1_SZ  = STAGES * STAGE1_SZ;   // 96 KB
static constexpr int STAGE2_SZ = 16384;
static constexpr int SMEM2_SZ  = STAGES * STAGE2_SZ;   // 48 KB

// ---------------- prep: fp16 hi/lo split, MLP=4, streaming cache hints ------
__global__ __launch_bounds__(256)
void split_all_kernel(const float* __restrict__ xq, const float* __restrict__ xk)
{
    const int which = blockIdx.y;          // 0 = Q, 1 = KV
    const float* x = which ? xk : xq;
    __half* hi = which ? g_kh : g_qh;
    __half* lo = which ? g_kl : g_ql;

    const size_t base = ((size_t)blockIdx.x * 256 + threadIdx.x) * 4;  // float4 idx
    float4 v[4];
#pragma unroll
    for (int i = 0; i < 4; i++) v[i] = __ldcs(((const float4*)x) + base + i);  // evict-first

    uint4 H[2], L[2];
#pragma unroll
    for (int i = 0; i < 4; i++) {
        __half2 h0 = __floats2half2_rn(v[i].x, v[i].y);
        __half2 h1 = __floats2half2_rn(v[i].z, v[i].w);
        const float2 g0 = __half22float2(h0);
        const float2 g1 = __half22float2(h1);
        __half2 l0 = __floats2half2_rn(v[i].x - g0.x, v[i].y - g0.y);
        __half2 l1 = __floats2half2_rn(v[i].z - g1.x, v[i].w - g1.y);
        ((uint32_t*)H)[2 * i]     = *(uint32_t*)&h0;
        ((uint32_t*)H)[2 * i + 1] = *(uint32_t*)&h1;
        ((uint32_t*)L)[2 * i]     = *(uint32_t*)&l0;
        ((uint32_t*)L)[2 * i + 1] = *(uint32_t*)&l1;
    }
    uint4* ph = (uint4*)(hi + base * 4);
    uint4* pl = (uint4*)(lo + base * 4);
    __stcs(ph, H[0]);     __stcs(ph + 1, H[1]);      // streaming stores
    __stcs(pl, L[0]);     __stcs(pl + 1, L[1]);
}

// ---------------- GEMM1 (NT): energy[c,d] = sum_n q[c,n] kv[d,n] -----------
// fp16 split operands, fp32 acc, 3 products (hh + hl + lh).
// 128x128 tile, BK=32, 3-stage cp.async pipeline, 2 CTAs/SM.
__global__ __launch_bounds__(256, 2)
void gemm1_kernel(const __half* __restrict__ Ah, const __half* __restrict__ Al,
                  const __half* __restrict__ Bh, const __half* __restrict__ Bl)
{
    extern __shared__ char smem[];
    const uint32_t sb = smem_u32(smem);
    const int tid = threadIdx.x, wid = tid >> 5, lane = tid & 31;
    const int b = blockIdx.z, row0 = blockIdx.y * 128, col0 = blockIdx.x * 128;
    const size_t bstr = (size_t)b * C_ * N_;

    const __half* srcs[4] = {
        Ah + bstr + (size_t)row0 * N_, Al + bstr + (size_t)row0 * N_,
        Bh + bstr + (size_t)col0 * N_, Bl + bstr + (size_t)col0 * N_ };

    auto load_stage = [&](int kb) {
        const uint32_t st = sb + (kb % STAGES) * STAGE1_SZ;
#pragma unroll
        for (int t = 0; t < 4; t++) {
            const __half* src = srcs[t] + kb * 32;
            const uint32_t tb = st + t * 8192;
#pragma unroll
            for (int i = 0; i < 2; i++) {
                const int idx = tid + i * 256;
                const int row = idx >> 2, ch = idx & 3;
                CP_ASYNC16(tb + offA(row, ch), src + (size_t)row * N_ + ch * 8);
            }
        }
    };

    float acc[4][4][4];
#pragma unroll
    for (int i = 0; i < 4; i++)
#pragma unroll
        for (int j = 0; j < 4; j++)
#pragma unroll
            for (int k = 0; k < 4; k++) acc[i][j][k] = 0.f;

    load_stage(0); CP_COMMIT();
    load_stage(1); CP_COMMIT();

    const int wm = wid >> 2, wn = wid & 3;
    constexpr int NKB = N_ / 32;   // 128

    for (int kb = 0; kb < NKB; kb++) {
        CP_WAIT1();
        __syncthreads();
        if (kb + 2 < NKB) load_stage(kb + 2);
        CP_COMMIT();
        const uint32_t sAh = sb + (kb % STAGES) * STAGE1_SZ;
        const uint32_t sAl = sAh + 8192, sBh = sAh + 16384, sBl = sAh + 24576;
#pragma unroll
        for (int ks = 0; ks < 2; ks++) {
            uint32_t afh[4][4], afl[4][4];
            {
                const int rb = wm * 64 + (lane & 7) + ((lane >> 3) & 1) * 8;
                const int ch = ks * 2 + (lane >> 4);
#pragma unroll
                for (int mt = 0; mt < 4; mt++) {
                    const uint32_t o = offA(rb + mt * 16, ch);
                    ldsm4(afh[mt], sAh + o);
                    ldsm4(afl[mt], sAl + o);
                }
            }
#pragma unroll
            for (int nt2 = 0; nt2 < 2; nt2++) {
                const int rb = wn * 32 + nt2 * 16 + (lane & 7) + ((lane >> 4) & 1) * 8;
                const int ch = ks * 2 + ((lane >> 3) & 1);
                const uint32_t o = offA(rb, ch);
                uint32_t bfh[4], bfl[4];
                ldsm4(bfh, sBh + o);
                ldsm4(bfl, sBl + o);
#pragma unroll
                for (int mt = 0; mt < 4; mt++) {
                    mma16816(acc[mt][nt2 * 2],     afh[mt], bfh);
                    mma16816(acc[mt][nt2 * 2 + 1], afh[mt], bfh + 2);
                    mma16816(acc[mt][nt2 * 2],     afh[mt], bfl);
                    mma16816(acc[mt][nt2 * 2 + 1], afh[mt], bfl + 2);
                    mma16816(acc[mt][nt2 * 2],     afl[mt], bfh);
                    mma16816(acc[mt][nt2 * 2 + 1], afl[mt], bfh + 2);
                }
            }
        }
    }

    // epilogue: fp32 store to g_energy (read exactly once -> streaming hint)
    float* Cm = g_energy + (size_t)b * C_ * C_;
    const int r0 = row0 + wm * 64 + (lane >> 2);
    const int c0g = col0 + wn * 32 + (lane & 3) * 2;
#pragma unroll
    for (int mt = 0; mt < 4; mt++)
#pragma unroll
        for (int nt = 0; nt < 4; nt++) {
            float* p = Cm + (size_t)(r0 + mt * 16) * C_ + c0g + nt * 8;
            __stcs((float2*)p, make_float2(acc[mt][nt][0], acc[mt][nt][1]));
            __stcs((float2*)(p + 8 * C_), make_float2(acc[mt][nt][2], acc[mt][nt][3]));
        }
}

// ---------------- softmax over 512 -> fp16 attention -----------------------
__global__ __launch_bounds__(128)
void softmax512_split_kernel()
{
    __shared__ float red[4];
    const size_t row = blockIdx.x;
    const float* e = g_energy + row * C_;
    const int t = threadIdx.x;

    float4 v = __ldcs(((const float4*)e) + t);    // energy read exactly once
    float mn = fminf(fminf(v.x, v.y), fminf(v.z, v.w));
#pragma unroll
    for (int o = 16; o; o >>= 1) mn = fminf(mn, __shfl_xor_sync(0xffffffffu, mn, o));
    if ((t & 31) == 0) red[t >> 5] = mn;
    __syncthreads();
    mn = fminf(fminf(red[0], red[1]), fminf(red[2], red[3]));

    float4 w;
    w.x = __expf(mn - v.x); w.y = __expf(mn - v.y);
    w.z = __expf(mn - v.z); w.w = __expf(mn - v.w);
    float s = (w.x + w.y) + (w.z + w.w);
#pragma unroll
    for (int o = 16; o; o >>= 1) s += __shfl_xor_sync(0xffffffffu, s, o);
    __syncthreads();
    if ((t & 31) == 0) red[t >> 5] = s;
    __syncthreads();
    const float inv = 1.f / (red[0] + red[1] + red[2] + red[3]);

    __half2* ah = (__half2*)(g_ah + row * C_);
    ah[2 * t]     = __halves2half2(__float2half(w.x * inv), __float2half(w.y * inv));
    ah[2 * t + 1] = __halves2half2(__float2half(w.z * inv), __float2half(w.w * inv));
}

// ---------------- GEMM2 (NN): out[c,n] = softmax64( sum_d att[c,d] kv[d,n] )
// A = attention fp16 [C,C] (k contig), B = kv hi [C,N] (trans-ldmatrix).
// Single product Ah*Bh. 128x128 tile, BK=32, warps 4x2 (32 rows x 64 cols),
// fused per-64-segment softmax epilogue.  (R8 config — best measured.)
__global__ __launch_bounds__(256, 2)
void gemm2_kernel(const __half* __restrict__ Bh, float* __restrict__ Out)
{
    extern __shared__ char smem[];
    const uint32_t sb = smem_u32(smem);
    const int tid = threadIdx.x, wid = tid >> 5, lane = tid & 31;
    const int b = blockIdx.z, row0 = blockIdx.y * 128, col0 = blockIdx.x * 128;

    const __half* aSrc = g_ah + (size_t)b * C_ * C_ + (size_t)row0 * C_;
    const __half* bSrc = Bh + (size_t)b * C_ * N_ + col0;

    auto load_stage = [&](int kb) {
        const uint32_t st = sb + (kb % STAGES) * STAGE2_SZ;
        {   // A tile (fp16 attention, A-type layout)
            const __half* src = aSrc + kb * 32;
#pragma unroll
            for (int i = 0; i < 2; i++) {
                const int idx = tid + i * 256;
                const int row = idx >> 2, ch = idx & 3;
                CP_ASYNC16(st + offA(row, ch), src + (size_t)row * C_ + ch * 8);
            }
        }
        {   // B tile (n-major layout)
            const __half* src = bSrc + (size_t)(kb * 32) * N_;
            const uint32_t tb = st + 8192;
#pragma unroll
            for (int i = 0; i < 2; i++) {
                const int idx = tid + i * 256;
                const int krow = idx >> 4, ch = idx & 15;
                CP_ASYNC16(tb + offB(krow, ch), src + (size_t)krow * N_ + ch * 8);
            }
        }
    };

    float acc[2][8][4];
#pragma unroll
    for (int i = 0; i < 2; i++)
#pragma unroll
        for (int j = 0; j < 8; j++)
#pragma unroll
            for (int k = 0; k < 4; k++) acc[i][j][k] = 0.f;

    load_stage(0); CP_COMMIT();
    load_stage(1); CP_COMMIT();

    const int wm = wid >> 1, wn = wid & 1;    // 4 x 2 warps
    constexpr int NKB = C_ / 32;   // 16

    for (int kb = 0; kb < NKB; kb++) {
        CP_WAIT1();
        __syncthreads();
        if (kb + 2 < NKB) load_stage(kb + 2);
        CP_COMMIT();
        const uint32_t sA = sb + (kb % STAGES) * STAGE2_SZ;
        const uint32_t sBh = sA + 8192;
#pragma unroll
        for (int ks = 0; ks < 2; ks++) {
            uint32_t afh[2][4];
            {
                const int rb = wm * 32 + (lane & 7) + ((lane >> 3) & 1) * 8;
                const int ch = ks * 2 + (lane >> 4);
#pragma unroll
                for (int mt = 0; mt < 2; mt++)
                    ldsm4(afh[mt], sA + offA(rb + mt * 16, ch));
            }
            const int krow = ks * 16 + (lane & 7) + ((lane >> 3) & 1) * 8;
#pragma unroll
            for (int nt2 = 0; nt2 < 4; nt2++) {
                const int ch = wn * 8 + nt2 * 2 + (lane >> 4);
                uint32_t bfh[4];
                ldsm4t(bfh, sBh + offB(krow, ch));
#pragma unroll
                for (int mt = 0; mt < 2; mt++) {
                    mma16816(acc[mt][nt2 * 2],     afh[mt], bfh);
                    mma16816(acc[mt][nt2 * 2 + 1], afh[mt], bfh + 2);
                }
            }
        }
    }

    // epilogue: fused softmax over this warp's 64-col segment.
#pragma unroll
    for (int mt = 0; mt < 2; mt++)
#pragma unroll
    for (int h = 0; h < 2; h++) {
        const int r = wm * 32 + mt * 16 + (lane >> 2) + h * 8;
        float* orow = Out + ((size_t)b * C_ + row0 + r) * N_ + col0 + wn * 64;
        float v[16];
#pragma unroll
        for (int j = 0; j < 8; j++) {
            v[2 * j]     = acc[mt][j][2 * h];
            v[2 * j + 1] = acc[mt][j][2 * h + 1];
        }
        float m = v[0];
#pragma unroll
        for (int j = 1; j < 16; j++) m = fmaxf(m, v[j]);
        m = fmaxf(m, __shfl_xor_sync(0xffffffffu, m, 1));
        m = fmaxf(m, __shfl_xor_sync(0xffffffffu, m, 2));
        float s = 0.f;
#pragma unroll
        for (int j = 0; j < 16; j++) { v[j] = __expf(v[j] - m); s += v[j]; }
        s += __shfl_xor_sync(0xffffffffu, s, 1);
        s += __shfl_xor_sync(0xffffffffu, s, 2);
        const float inv = 1.f / s;
#pragma unroll
        for (int j = 0; j < 8; j++) {
            float* p = orow + j * 8 + (lane & 3) * 2;
            __stcs((float2*)p, make_float2(v[2 * j] * inv, v[2 * j + 1] * inv));
        }
    }
}

// ---------------------------------------------------------------------------
extern "C" void kernel_launch(void* const* d_in, const int* in_sizes, int n_in,
                              void* d_out, int out_size)
{
    const float* x_training = (const float*)d_in[0];  // KV
    const float* x_pre      = (const float*)d_in[1];  // Q
    float* out = (float*)d_out;

    cudaFuncSetAttribute(gemm1_kernel, cudaFuncAttributeMaxDynamicSharedMemorySize, SMEM1_SZ);
    cudaFuncSetAttribute(gemm2_kernel, cudaFuncAttributeMaxDynamicSharedMemorySize, SMEM2_SZ);

    __half *qh, *ql, *kh, *kl;
    cudaGetSymbolAddress((void**)&qh, g_qh);
    cudaGetSymbolAddress((void**)&ql, g_ql);
    cudaGetSymbolAddress((void**)&kh, g_kh);
    cudaGetSymbolAddress((void**)&kl, g_kl);

    const int nblk = B_ * C_ * N_ / 16 / 256;   // 16 floats per thread

    // 1) fp16 hi/lo splits of Q and KV (MLP=4, streaming cache policy)
    split_all_kernel<<<dim3(nblk, 2), 256>>>(x_pre, x_training);
    // 2) energy = Q @ KV^T   (HMMA, fp16-split 3-product)
    gemm1_kernel<<<dim3(C_ / 128, C_ / 128, B_), 256, SMEM1_SZ>>>(qh, ql, kh, kl);
    // 3) attention = softmax(min - energy) -> fp16
    softmax512_split_kernel<<<B_ * C_, 128>>>();
    // 4) out = softmax64(attention @ KV)   (HMMA single-product + fused softmax)
    gemm2_kernel<<<dim3(N_ / 128, C_ / 128, B_), 256, SMEM2_SZ>>>(kh, out);
}

// round 16
// speedup vs baseline: 1.0129x; 1.0129x over previous
#include <cuda_runtime.h>
#include <cuda_fp16.h>
#include <cstdint>

#define B_ 16
#define C_ 512
#define N_ 4096   // H*W
#define W_ 64

// ---------------- scratch (__device__ globals: allocation-free rule) --------
__device__ __half g_qh[(size_t)B_ * C_ * N_];   // 67 MB each
__device__ __half g_ql[(size_t)B_ * C_ * N_];
__device__ __half g_kh[(size_t)B_ * C_ * N_];
__device__ __half g_kl[(size_t)B_ * C_ * N_];
__device__ __half g_ah[(size_t)B_ * C_ * C_];   // attention (fp16)
__device__ float  g_energy[(size_t)B_ * C_ * C_];

// ---------------- plain-target PTX helpers ----------------------------------
__device__ __forceinline__ uint32_t smem_u32(const void* p) {
    uint32_t a;
    asm("{ .reg .u64 t; cvta.to.shared.u64 t, %1; cvt.u32.u64 %0, t; }" : "=r"(a) : "l"(p));
    return a;
}
__device__ __forceinline__ void ldsm4(uint32_t* r, uint32_t addr) {
    asm volatile("ldmatrix.sync.aligned.m8n8.x4.shared.b16 {%0,%1,%2,%3}, [%4];"
                 : "=r"(r[0]), "=r"(r[1]), "=r"(r[2]), "=r"(r[3]) : "r"(addr));
}
__device__ __forceinline__ void ldsm4t(uint32_t* r, uint32_t addr) {
    asm volatile("ldmatrix.sync.aligned.m8n8.x4.trans.shared.b16 {%0,%1,%2,%3}, [%4];"
                 : "=r"(r[0]), "=r"(r[1]), "=r"(r[2]), "=r"(r[3]) : "r"(addr));
}
__device__ __forceinline__ void mma16816(float* d, const uint32_t* a, const uint32_t* b) {
    asm volatile(
        "mma.sync.aligned.m16n8k16.row.col.f32.f16.f16.f32 "
        "{%0,%1,%2,%3}, {%4,%5,%6,%7}, {%8,%9}, {%0,%1,%2,%3};"
        : "+f"(d[0]), "+f"(d[1]), "+f"(d[2]), "+f"(d[3])
        : "r"(a[0]), "r"(a[1]), "r"(a[2]), "r"(a[3]), "r"(b[0]), "r"(b[1]));
}
#define CP_ASYNC16(s, g) \
    asm volatile("cp.async.cg.shared.global [%0], [%1], 16;" :: "r"(s), "l"(g))
#define CP_COMMIT()  asm volatile("cp.async.commit_group;" ::: "memory")
#define CP_WAIT1()   asm volatile("cp.async.wait_group 1;" ::: "memory")

// Swizzled byte offsets inside an 8 KB tile.
// A-type tile: 128 rows x 32 halves (64 B/row); chunk = 16 B.
__device__ __forceinline__ uint32_t offA(int row, int ch) {
    return row * 64 + ((ch ^ ((row >> 1) & 3)) * 16);
}
// B-type tile (n-major): 32 rows x 128 halves (256 B/row).
__device__ __forceinline__ uint32_t offB(int krow, int ch) {
    return krow * 256 + ((ch ^ (krow & 7)) * 16);
}

static constexpr int STAGES = 3;
// gemm1: 4 tiles x 8 KB; gemm2: 2 tiles x 8 KB (A + Bh only)
static constexpr int STAGE1_SZ = 32768;
static constexpr int SMEM1_SZ  = STAGES * STAGE1_SZ;   // 96 KB
static constexpr int STAGE2_SZ = 16384;
static constexpr int SMEM2_SZ  = STAGES * STAGE2_SZ;   // 48 KB

// ---------------- prep: fp16 hi/lo split (both tensors, one launch) ---------
__global__ __launch_bounds__(256)
void split_all_kernel(const float* __restrict__ xq, const float* __restrict__ xk)
{
    const int which = blockIdx.y;          // 0 = Q, 1 = KV
    const float* x = which ? xk : xq;
    __half* hi = which ? g_kh : g_qh;
    __half* lo = which ? g_kl : g_ql;

    const size_t i = (size_t)blockIdx.x * 256 + threadIdx.x;
    const float4 v = ((const float4*)x)[i];
    const __half h0 = __float2half(v.x), h1 = __float2half(v.y);
    const __half h2 = __float2half(v.z), h3 = __float2half(v.w);
    const __half l0 = __float2half(v.x - __half2float(h0));
    const __half l1 = __float2half(v.y - __half2float(h1));
    const __half l2 = __float2half(v.z - __half2float(h2));
    const __half l3 = __float2half(v.w - __half2float(h3));
    ((__half2*)hi)[2 * i]     = __halves2half2(h0, h1);
    ((__half2*)hi)[2 * i + 1] = __halves2half2(h2, h3);
    ((__half2*)lo)[2 * i]     = __halves2half2(l0, l1);
    ((__half2*)lo)[2 * i + 1] = __halves2half2(l2, l3);
}

// ---------------- GEMM1 (NT): energy[c,d] = sum_n q[c,n] kv[d,n] -----------
// fp16 split operands, fp32 acc, 3 products (hh + hl + lh).
// 128x128 tile, BK=32, 3-stage cp.async pipeline, 2 CTAs/SM.
__global__ __launch_bounds__(256, 2)
void gemm1_kernel(const __half* __restrict__ Ah, const __half* __restrict__ Al,
                  const __half* __restrict__ Bh, const __half* __restrict__ Bl)
{
    extern __shared__ char smem[];
    const uint32_t sb = smem_u32(smem);
    const int tid = threadIdx.x, wid = tid >> 5, lane = tid & 31;
    const int b = blockIdx.z, row0 = blockIdx.y * 128, col0 = blockIdx.x * 128;
    const size_t bstr = (size_t)b * C_ * N_;

    const __half* srcs[4] = {
        Ah + bstr + (size_t)row0 * N_, Al + bstr + (size_t)row0 * N_,
        Bh + bstr + (size_t)col0 * N_, Bl + bstr + (size_t)col0 * N_ };

    auto load_stage = [&](int kb) {
        const uint32_t st = sb + (kb % STAGES) * STAGE1_SZ;
#pragma unroll
        for (int t = 0; t < 4; t++) {
            const __half* src = srcs[t] + kb * 32;
            const uint32_t tb = st + t * 8192;
#pragma unroll
            for (int i = 0; i < 2; i++) {
                const int idx = tid + i * 256;
                const int row = idx >> 2, ch = idx & 3;
                CP_ASYNC16(tb + offA(row, ch), src + (size_t)row * N_ + ch * 8);
            }
        }
    };

    float acc[4][4][4];
#pragma unroll
    for (int i = 0; i < 4; i++)
#pragma unroll
        for (int j = 0; j < 4; j++)
#pragma unroll
            for (int k = 0; k < 4; k++) acc[i][j][k] = 0.f;

    load_stage(0); CP_COMMIT();
    load_stage(1); CP_COMMIT();

    const int wm = wid >> 2, wn = wid & 3;
    constexpr int NKB = N_ / 32;   // 128

    for (int kb = 0; kb < NKB; kb++) {
        CP_WAIT1();
        __syncthreads();
        if (kb + 2 < NKB) load_stage(kb + 2);
        CP_COMMIT();
        const uint32_t sAh = sb + (kb % STAGES) * STAGE1_SZ;
        const uint32_t sAl = sAh + 8192, sBh = sAh + 16384, sBl = sAh + 24576;
#pragma unroll
        for (int ks = 0; ks < 2; ks++) {
            uint32_t afh[4][4], afl[4][4];
            {
                const int rb = wm * 64 + (lane & 7) + ((lane >> 3) & 1) * 8;
                const int ch = ks * 2 + (lane >> 4);
#pragma unroll
                for (int mt = 0; mt < 4; mt++) {
                    const uint32_t o = offA(rb + mt * 16, ch);
                    ldsm4(afh[mt], sAh + o);
                    ldsm4(afl[mt], sAl + o);
                }
            }
#pragma unroll
            for (int nt2 = 0; nt2 < 2; nt2++) {
                const int rb = wn * 32 + nt2 * 16 + (lane & 7) + ((lane >> 4) & 1) * 8;
                const int ch = ks * 2 + ((lane >> 3) & 1);
                const uint32_t o = offA(rb, ch);
                uint32_t bfh[4], bfl[4];
                ldsm4(bfh, sBh + o);
                ldsm4(bfl, sBl + o);
#pragma unroll
                for (int mt = 0; mt < 4; mt++) {
                    mma16816(acc[mt][nt2 * 2],     afh[mt], bfh);
                    mma16816(acc[mt][nt2 * 2 + 1], afh[mt], bfh + 2);
                    mma16816(acc[mt][nt2 * 2],     afh[mt], bfl);
                    mma16816(acc[mt][nt2 * 2 + 1], afh[mt], bfl + 2);
                    mma16816(acc[mt][nt2 * 2],     afl[mt], bfh);
                    mma16816(acc[mt][nt2 * 2 + 1], afl[mt], bfh + 2);
                }
            }
        }
    }

    // epilogue: plain fp32 store to g_energy
    float* Cm = g_energy + (size_t)b * C_ * C_;
    const int r0 = row0 + wm * 64 + (lane >> 2);
    const int c0g = col0 + wn * 32 + (lane & 3) * 2;
#pragma unroll
    for (int mt = 0; mt < 4; mt++)
#pragma unroll
        for (int nt = 0; nt < 4; nt++) {
            float* p = Cm + (size_t)(r0 + mt * 16) * C_ + c0g + nt * 8;
            *(float2*)p = make_float2(acc[mt][nt][0], acc[mt][nt][1]);
            *(float2*)(p + 8 * C_) = make_float2(acc[mt][nt][2], acc[mt][nt][3]);
        }
}

// ---------------- softmax over 512 -> fp16 attention -----------------------
__global__ __launch_bounds__(128)
void softmax512_split_kernel()
{
    __shared__ float red[4];
    const size_t row = blockIdx.x;
    const float* e = g_energy + row * C_;
    const int t = threadIdx.x;

    float4 v = ((const float4*)e)[t];
    float mn = fminf(fminf(v.x, v.y), fminf(v.z, v.w));
#pragma unroll
    for (int o = 16; o; o >>= 1) mn = fminf(mn, __shfl_xor_sync(0xffffffffu, mn, o));
    if ((t & 31) == 0) red[t >> 5] = mn;
    __syncthreads();
    mn = fminf(fminf(red[0], red[1]), fminf(red[2], red[3]));

    float4 w;
    w.x = __expf(mn - v.x); w.y = __expf(mn - v.y);
    w.z = __expf(mn - v.z); w.w = __expf(mn - v.w);
    float s = (w.x + w.y) + (w.z + w.w);
#pragma unroll
    for (int o = 16; o; o >>= 1) s += __shfl_xor_sync(0xffffffffu, s, o);
    __syncthreads();
    if ((t & 31) == 0) red[t >> 5] = s;
    __syncthreads();
    const float inv = 1.f / (red[0] + red[1] + red[2] + red[3]);

    __half2* ah = (__half2*)(g_ah + row * C_);
    ah[2 * t]     = __halves2half2(__float2half(w.x * inv), __float2half(w.y * inv));
    ah[2 * t + 1] = __halves2half2(__float2half(w.z * inv), __float2half(w.w * inv));
}

// ---------------- GEMM2 (NN): out[c,n] = softmax64( sum_d att[c,d] kv[d,n] )
// A = attention fp16 [C,C] (k contig), B = kv hi [C,N] (trans-ldmatrix).
// Single product Ah*Bh. 128x128 tile, BK=32, warps 4x2 (32 rows x 64 cols),
// fused per-64-segment softmax epilogue.
__global__ __launch_bounds__(256, 2)
void gemm2_kernel(const __half* __restrict__ Bh, float* __restrict__ Out)
{
    extern __shared__ char smem[];
    const uint32_t sb = smem_u32(smem);
    const int tid = threadIdx.x, wid = tid >> 5, lane = tid & 31;
    const int b = blockIdx.z, row0 = blockIdx.y * 128, col0 = blockIdx.x * 128;

    const __half* aSrc = g_ah + (size_t)b * C_ * C_ + (size_t)row0 * C_;
    const __half* bSrc = Bh + (size_t)b * C_ * N_ + col0;

    auto load_stage = [&](int kb) {
        const uint32_t st = sb + (kb % STAGES) * STAGE2_SZ;
        {   // A tile (fp16 attention, A-type layout)
            const __half* src = aSrc + kb * 32;
#pragma unroll
            for (int i = 0; i < 2; i++) {
                const int idx = tid + i * 256;
                const int row = idx >> 2, ch = idx & 3;
                CP_ASYNC16(st + offA(row, ch), src + (size_t)row * C_ + ch * 8);
            }
        }
        {   // B tile (n-major layout)
            const __half* src = bSrc + (size_t)(kb * 32) * N_;
            const uint32_t tb = st + 8192;
#pragma unroll
            for (int i = 0; i < 2; i++) {
                const int idx = tid + i * 256;
                const int krow = idx >> 4, ch = idx & 15;
                CP_ASYNC16(tb + offB(krow, ch), src + (size_t)krow * N_ + ch * 8);
            }
        }
    };

    float acc[2][8][4];
#pragma unroll
    for (int i = 0; i < 2; i++)
#pragma unroll
        for (int j = 0; j < 8; j++)
#pragma unroll
            for (int k = 0; k < 4; k++) acc[i][j][k] = 0.f;

    load_stage(0); CP_COMMIT();
    load_stage(1); CP_COMMIT();

    const int wm = wid >> 1, wn = wid & 1;    // 4 x 2 warps
    constexpr int NKB = C_ / 32;   // 16

    for (int kb = 0; kb < NKB; kb++) {
        CP_WAIT1();
        __syncthreads();
        if (kb + 2 < NKB) load_stage(kb + 2);
        CP_COMMIT();
        const uint32_t sA = sb + (kb % STAGES) * STAGE2_SZ;
        const uint32_t sBh = sA + 8192;
#pragma unroll
        for (int ks = 0; ks < 2; ks++) {
            uint32_t afh[2][4];
            {
                const int rb = wm * 32 + (lane & 7) + ((lane >> 3) & 1) * 8;
                const int ch = ks * 2 + (lane >> 4);
#pragma unroll
                for (int mt = 0; mt < 2; mt++)
                    ldsm4(afh[mt], sA + offA(rb + mt * 16, ch));
            }
            const int krow = ks * 16 + (lane & 7) + ((lane >> 3) & 1) * 8;
#pragma unroll
            for (int nt2 = 0; nt2 < 4; nt2++) {
                const int ch = wn * 8 + nt2 * 2 + (lane >> 4);
                uint32_t bfh[4];
                ldsm4t(bfh, sBh + offB(krow, ch));
#pragma unroll
                for (int mt = 0; mt < 2; mt++) {
                    mma16816(acc[mt][nt2 * 2],     afh[mt], bfh);
                    mma16816(acc[mt][nt2 * 2 + 1], afh[mt], bfh + 2);
                }
            }
        }
    }

    // epilogue: fused softmax over this warp's 64-col segment.
#pragma unroll
    for (int mt = 0; mt < 2; mt++)
#pragma unroll
    for (int h = 0; h < 2; h++) {
        const int r = wm * 32 + mt * 16 + (lane >> 2) + h * 8;
        float* orow = Out + ((size_t)b * C_ + row0 + r) * N_ + col0 + wn * 64;
        float v[16];
#pragma unroll
        for (int j = 0; j < 8; j++) {
            v[2 * j]     = acc[mt][j][2 * h];
            v[2 * j + 1] = acc[mt][j][2 * h + 1];
        }
        float m = v[0];
#pragma unroll
        for (int j = 1; j < 16; j++) m = fmaxf(m, v[j]);
        m = fmaxf(m, __shfl_xor_sync(0xffffffffu, m, 1));
        m = fmaxf(m, __shfl_xor_sync(0xffffffffu, m, 2));
        float s = 0.f;
#pragma unroll
        for (int j = 0; j < 16; j++) { v[j] = __expf(v[j] - m); s += v[j]; }
        s += __shfl_xor_sync(0xffffffffu, s, 1);
        s += __shfl_xor_sync(0xffffffffu, s, 2);
        const float inv = 1.f / s;
#pragma unroll
        for (int j = 0; j < 8; j++) {
            float* p = orow + j * 8 + (lane & 3) * 2;
            *(float2*)p = make_float2(v[2 * j] * inv, v[2 * j + 1] * inv);
        }
    }
}

// ---------------------------------------------------------------------------
extern "C" void kernel_launch(void* const* d_in, const int* in_sizes, int n_in,
                              void* d_out, int out_size)
{
    const float* x_training = (const float*)d_in[0];  // KV
    const float* x_pre      = (const float*)d_in[1];  // Q
    float* out = (float*)d_out;

    cudaFuncSetAttribute(gemm1_kernel, cudaFuncAttributeMaxDynamicSharedMemorySize, SMEM1_SZ);
    cudaFuncSetAttribute(gemm2_kernel, cudaFuncAttributeMaxDynamicSharedMemorySize, SMEM2_SZ);

    __half *qh, *ql, *kh, *kl;
    cudaGetSymbolAddress((void**)&qh, g_qh);
    cudaGetSymbolAddress((void**)&ql, g_ql);
    cudaGetSymbolAddress((void**)&kh, g_kh);
    cudaGetSymbolAddress((void**)&kl, g_kl);

    const int nvec = B_ * C_ * N_ / 4;    // float4s per tensor

    // 1) fp16 hi/lo splits of Q and KV
    split_all_kernel<<<dim3(nvec / 256, 2), 256>>>(x_pre, x_training);
    // 2) energy = Q @ KV^T   (HMMA, fp16-split 3-product)
    gemm1_kernel<<<dim3(C_ / 128, C_ / 128, B_), 256, SMEM1_SZ>>>(qh, ql, kh, kl);
    // 3) attention = softmax(min - energy) -> fp16
    softmax512_split_kernel<<<B_ * C_, 128>>>();
    // 4) out = softmax64(attention @ KV)   (HMMA single-product + fused softmax)
    gemm2_kernel<<<dim3(N_ / 128, C_ / 128, B_), 256, SMEM2_SZ>>>(kh, out);
}

// round 17
// speedup vs baseline: 1.1231x; 1.1087x over previous
#include <cuda_runtime.h>
#include <cuda_fp16.h>
#include <cstdint>

#define B_ 16
#define C_ 512
#define N_ 4096   // H*W
#define W_ 64
#define HB_ 8     // batches per pipeline half

// ---------------- scratch (__device__ globals: allocation-free rule) --------
__device__ __half g_qh[(size_t)B_ * C_ * N_];   // 67 MB each
__device__ __half g_ql[(size_t)B_ * C_ * N_];
__device__ __half g_kh[(size_t)B_ * C_ * N_];
__device__ __half g_kl[(size_t)B_ * C_ * N_];
__device__ __half g_ah[(size_t)B_ * C_ * C_];   // attention (fp16)
__device__ float  g_energy[(size_t)B_ * C_ * C_];

// ---------------- plain-target PTX helpers ----------------------------------
__device__ __forceinline__ uint32_t smem_u32(const void* p) {
    uint32_t a;
    asm("{ .reg .u64 t; cvta.to.shared.u64 t, %1; cvt.u32.u64 %0, t; }" : "=r"(a) : "l"(p));
    return a;
}
__device__ __forceinline__ void ldsm4(uint32_t* r, uint32_t addr) {
    asm volatile("ldmatrix.sync.aligned.m8n8.x4.shared.b16 {%0,%1,%2,%3}, [%4];"
                 : "=r"(r[0]), "=r"(r[1]), "=r"(r[2]), "=r"(r[3]) : "r"(addr));
}
__device__ __forceinline__ void ldsm4t(uint32_t* r, uint32_t addr) {
    asm volatile("ldmatrix.sync.aligned.m8n8.x4.trans.shared.b16 {%0,%1,%2,%3}, [%4];"
                 : "=r"(r[0]), "=r"(r[1]), "=r"(r[2]), "=r"(r[3]) : "r"(addr));
}
__device__ __forceinline__ void mma16816(float* d, const uint32_t* a, const uint32_t* b) {
    asm volatile(
        "mma.sync.aligned.m16n8k16.row.col.f32.f16.f16.f32 "
        "{%0,%1,%2,%3}, {%4,%5,%6,%7}, {%8,%9}, {%0,%1,%2,%3};"
        : "+f"(d[0]), "+f"(d[1]), "+f"(d[2]), "+f"(d[3])
        : "r"(a[0]), "r"(a[1]), "r"(a[2]), "r"(a[3]), "r"(b[0]), "r"(b[1]));
}
#define CP_ASYNC16(s, g) \
    asm volatile("cp.async.cg.shared.global [%0], [%1], 16;" :: "r"(s), "l"(g))
#define CP_COMMIT()  asm volatile("cp.async.commit_group;" ::: "memory")
#define CP_WAIT1()   asm volatile("cp.async.wait_group 1;" ::: "memory")

// Swizzled byte offsets inside an 8 KB tile.
// A-type tile: 128 rows x 32 halves (64 B/row); chunk = 16 B.
__device__ __forceinline__ uint32_t offA(int row, int ch) {
    return row * 64 + ((ch ^ ((row >> 1) & 3)) * 16);
}
// B-type tile (n-major): 32 rows x 128 halves (256 B/row).
__device__ __forceinline__ uint32_t offB(int krow, int ch) {
    return krow * 256 + ((ch ^ (krow & 7)) * 16);
}

static constexpr int STAGES = 3;
static constexpr int STAGE1_SZ = 32768;
static constexpr int SMEM1_SZ  = STAGES * STAGE1_SZ;   // 96 KB
static constexpr int STAGE2_SZ = 16384;
static constexpr int SMEM2_SZ  = STAGES * STAGE2_SZ;   // 48 KB

// ---------------- prep: fp16 hi/lo split (half-batch) -----------------------
__global__ __launch_bounds__(256)
void split_all_kernel(const float* __restrict__ xq, const float* __restrict__ xk,
                      int bz0)
{
    const int which = blockIdx.y;          // 0 = Q, 1 = KV
    const size_t off = (size_t)bz0 * C_ * N_;
    const float* x = (which ? xk : xq) + off;
    __half* hi = (which ? g_kh : g_qh) + off;
    __half* lo = (which ? g_kl : g_ql) + off;

    const size_t i = (size_t)blockIdx.x * 256 + threadIdx.x;
    const float4 v = ((const float4*)x)[i];
    const __half h0 = __float2half(v.x), h1 = __float2half(v.y);
    const __half h2 = __float2half(v.z), h3 = __float2half(v.w);
    const __half l0 = __float2half(v.x - __half2float(h0));
    const __half l1 = __float2half(v.y - __half2float(h1));
    const __half l2 = __float2half(v.z - __half2float(h2));
    const __half l3 = __float2half(v.w - __half2float(h3));
    ((__half2*)hi)[2 * i]     = __halves2half2(h0, h1);
    ((__half2*)hi)[2 * i + 1] = __halves2half2(h2, h3);
    ((__half2*)lo)[2 * i]     = __halves2half2(l0, l1);
    ((__half2*)lo)[2 * i + 1] = __halves2half2(l2, l3);
}

// ---------------- GEMM1 (NT): energy[c,d] = sum_n q[c,n] kv[d,n] -----------
__global__ __launch_bounds__(256, 2)
void gemm1_kernel(const __half* __restrict__ Ah, const __half* __restrict__ Al,
                  const __half* __restrict__ Bh, const __half* __restrict__ Bl,
                  int bz0)
{
    extern __shared__ char smem[];
    const uint32_t sb = smem_u32(smem);
    const int tid = threadIdx.x, wid = tid >> 5, lane = tid & 31;
    const int b = bz0 + blockIdx.z, row0 = blockIdx.y * 128, col0 = blockIdx.x * 128;
    const size_t bstr = (size_t)b * C_ * N_;

    const __half* srcs[4] = {
        Ah + bstr + (size_t)row0 * N_, Al + bstr + (size_t)row0 * N_,
        Bh + bstr + (size_t)col0 * N_, Bl + bstr + (size_t)col0 * N_ };

    auto load_stage = [&](int kb) {
        const uint32_t st = sb + (kb % STAGES) * STAGE1_SZ;
#pragma unroll
        for (int t = 0; t < 4; t++) {
            const __half* src = srcs[t] + kb * 32;
            const uint32_t tb = st + t * 8192;
#pragma unroll
            for (int i = 0; i < 2; i++) {
                const int idx = tid + i * 256;
                const int row = idx >> 2, ch = idx & 3;
                CP_ASYNC16(tb + offA(row, ch), src + (size_t)row * N_ + ch * 8);
            }
        }
    };

    float acc[4][4][4];
#pragma unroll
    for (int i = 0; i < 4; i++)
#pragma unroll
        for (int j = 0; j < 4; j++)
#pragma unroll
            for (int k = 0; k < 4; k++) acc[i][j][k] = 0.f;

    load_stage(0); CP_COMMIT();
    load_stage(1); CP_COMMIT();

    const int wm = wid >> 2, wn = wid & 3;
    constexpr int NKB = N_ / 32;   // 128

    for (int kb = 0; kb < NKB; kb++) {
        CP_WAIT1();
        __syncthreads();
        if (kb + 2 < NKB) load_stage(kb + 2);
        CP_COMMIT();
        const uint32_t sAh = sb + (kb % STAGES) * STAGE1_SZ;
        const uint32_t sAl = sAh + 8192, sBh = sAh + 16384, sBl = sAh + 24576;
#pragma unroll
        for (int ks = 0; ks < 2; ks++) {
            uint32_t afh[4][4], afl[4][4];
            {
                const int rb = wm * 64 + (lane & 7) + ((lane >> 3) & 1) * 8;
                const int ch = ks * 2 + (lane >> 4);
#pragma unroll
                for (int mt = 0; mt < 4; mt++) {
                    const uint32_t o = offA(rb + mt * 16, ch);
                    ldsm4(afh[mt], sAh + o);
                    ldsm4(afl[mt], sAl + o);
                }
            }
#pragma unroll
            for (int nt2 = 0; nt2 < 2; nt2++) {
                const int rb = wn * 32 + nt2 * 16 + (lane & 7) + ((lane >> 4) & 1) * 8;
                const int ch = ks * 2 + ((lane >> 3) & 1);
                const uint32_t o = offA(rb, ch);
                uint32_t bfh[4], bfl[4];
                ldsm4(bfh, sBh + o);
                ldsm4(bfl, sBl + o);
#pragma unroll
                for (int mt = 0; mt < 4; mt++) {
                    mma16816(acc[mt][nt2 * 2],     afh[mt], bfh);
                    mma16816(acc[mt][nt2 * 2 + 1], afh[mt], bfh + 2);
                    mma16816(acc[mt][nt2 * 2],     afh[mt], bfl);
                    mma16816(acc[mt][nt2 * 2 + 1], afh[mt], bfl + 2);
                    mma16816(acc[mt][nt2 * 2],     afl[mt], bfh);
                    mma16816(acc[mt][nt2 * 2 + 1], afl[mt], bfh + 2);
                }
            }
        }
    }

    // epilogue: plain fp32 store to g_energy
    float* Cm = g_energy + (size_t)b * C_ * C_;
    const int r0 = row0 + wm * 64 + (lane >> 2);
    const int c0g = col0 + wn * 32 + (lane & 3) * 2;
#pragma unroll
    for (int mt = 0; mt < 4; mt++)
#pragma unroll
        for (int nt = 0; nt < 4; nt++) {
            float* p = Cm + (size_t)(r0 + mt * 16) * C_ + c0g + nt * 8;
            *(float2*)p = make_float2(acc[mt][nt][0], acc[mt][nt][1]);
            *(float2*)(p + 8 * C_) = make_float2(acc[mt][nt][2], acc[mt][nt][3]);
        }
}

// ---------------- softmax over 512 -> fp16 attention (half-batch) ----------
__global__ __launch_bounds__(128)
void softmax512_split_kernel(int row0)
{
    __shared__ float red[4];
    const size_t row = (size_t)row0 + blockIdx.x;
    const float* e = g_energy + row * C_;
    const int t = threadIdx.x;

    float4 v = ((const float4*)e)[t];
    float mn = fminf(fminf(v.x, v.y), fminf(v.z, v.w));
#pragma unroll
    for (int o = 16; o; o >>= 1) mn = fminf(mn, __shfl_xor_sync(0xffffffffu, mn, o));
    if ((t & 31) == 0) red[t >> 5] = mn;
    __syncthreads();
    mn = fminf(fminf(red[0], red[1]), fminf(red[2], red[3]));

    float4 w;
    w.x = __expf(mn - v.x); w.y = __expf(mn - v.y);
    w.z = __expf(mn - v.z); w.w = __expf(mn - v.w);
    float s = (w.x + w.y) + (w.z + w.w);
#pragma unroll
    for (int o = 16; o; o >>= 1) s += __shfl_xor_sync(0xffffffffu, s, o);
    __syncthreads();
    if ((t & 31) == 0) red[t >> 5] = s;
    __syncthreads();
    const float inv = 1.f / (red[0] + red[1] + red[2] + red[3]);

    __half2* ah = (__half2*)(g_ah + row * C_);
    ah[2 * t]     = __halves2half2(__float2half(w.x * inv), __float2half(w.y * inv));
    ah[2 * t + 1] = __halves2half2(__float2half(w.z * inv), __float2half(w.w * inv));
}

// ---------------- GEMM2 (NN): out[c,n] = softmax64( sum_d att[c,d] kv[d,n] )
__global__ __launch_bounds__(256, 2)
void gemm2_kernel(const __half* __restrict__ Bh, float* __restrict__ Out, int bz0)
{
    extern __shared__ char smem[];
    const uint32_t sb = smem_u32(smem);
    const int tid = threadIdx.x, wid = tid >> 5, lane = tid & 31;
    const int b = bz0 + blockIdx.z, row0 = blockIdx.y * 128, col0 = blockIdx.x * 128;

    const __half* aSrc = g_ah + (size_t)b * C_ * C_ + (size_t)row0 * C_;
    const __half* bSrc = Bh + (size_t)b * C_ * N_ + col0;

    auto load_stage = [&](int kb) {
        const uint32_t st = sb + (kb % STAGES) * STAGE2_SZ;
        {   // A tile (fp16 attention, A-type layout)
            const __half* src = aSrc + kb * 32;
#pragma unroll
            for (int i = 0; i < 2; i++) {
                const int idx = tid + i * 256;
                const int row = idx >> 2, ch = idx & 3;
                CP_ASYNC16(st + offA(row, ch), src + (size_t)row * C_ + ch * 8);
            }
        }
        {   // B tile (n-major layout)
            const __half* src = bSrc + (size_t)(kb * 32) * N_;
            const uint32_t tb = st + 8192;
#pragma unroll
            for (int i = 0; i < 2; i++) {
                const int idx = tid + i * 256;
                const int krow = idx >> 4, ch = idx & 15;
                CP_ASYNC16(tb + offB(krow, ch), src + (size_t)krow * N_ + ch * 8);
            }
        }
    };

    float acc[2][8][4];
#pragma unroll
    for (int i = 0; i < 2; i++)
#pragma unroll
        for (int j = 0; j < 8; j++)
#pragma unroll
            for (int k = 0; k < 4; k++) acc[i][j][k] = 0.f;

    load_stage(0); CP_COMMIT();
    load_stage(1); CP_COMMIT();

    const int wm = wid >> 1, wn = wid & 1;    // 4 x 2 warps
    constexpr int NKB = C_ / 32;   // 16

    for (int kb = 0; kb < NKB; kb++) {
        CP_WAIT1();
        __syncthreads();
        if (kb + 2 < NKB) load_stage(kb + 2);
        CP_COMMIT();
        const uint32_t sA = sb + (kb % STAGES) * STAGE2_SZ;
        const uint32_t sBh = sA + 8192;
#pragma unroll
        for (int ks = 0; ks < 2; ks++) {
            uint32_t afh[2][4];
            {
                const int rb = wm * 32 + (lane & 7) + ((lane >> 3) & 1) * 8;
                const int ch = ks * 2 + (lane >> 4);
#pragma unroll
                for (int mt = 0; mt < 2; mt++)
                    ldsm4(afh[mt], sA + offA(rb + mt * 16, ch));
            }
            const int krow = ks * 16 + (lane & 7) + ((lane >> 3) & 1) * 8;
#pragma unroll
            for (int nt2 = 0; nt2 < 4; nt2++) {
                const int ch = wn * 8 + nt2 * 2 + (lane >> 4);
                uint32_t bfh[4];
                ldsm4t(bfh, sBh + offB(krow, ch));
#pragma unroll
                for (int mt = 0; mt < 2; mt++) {
                    mma16816(acc[mt][nt2 * 2],     afh[mt], bfh);
                    mma16816(acc[mt][nt2 * 2 + 1], afh[mt], bfh + 2);
                }
            }
        }
    }

    // epilogue: fused softmax over this warp's 64-col segment.
#pragma unroll
    for (int mt = 0; mt < 2; mt++)
#pragma unroll
    for (int h = 0; h < 2; h++) {
        const int r = wm * 32 + mt * 16 + (lane >> 2) + h * 8;
        float* orow = Out + ((size_t)b * C_ + row0 + r) * N_ + col0 + wn * 64;
        float v[16];
#pragma unroll
        for (int j = 0; j < 8; j++) {
            v[2 * j]     = acc[mt][j][2 * h];
            v[2 * j + 1] = acc[mt][j][2 * h + 1];
        }
        float m = v[0];
#pragma unroll
        for (int j = 1; j < 16; j++) m = fmaxf(m, v[j]);
        m = fmaxf(m, __shfl_xor_sync(0xffffffffu, m, 1));
        m = fmaxf(m, __shfl_xor_sync(0xffffffffu, m, 2));
        float s = 0.f;
#pragma unroll
        for (int j = 0; j < 16; j++) { v[j] = __expf(v[j] - m); s += v[j]; }
        s += __shfl_xor_sync(0xffffffffu, s, 1);
        s += __shfl_xor_sync(0xffffffffu, s, 2);
        const float inv = 1.f / s;
#pragma unroll
        for (int j = 0; j < 8; j++) {
            float* p = orow + j * 8 + (lane & 3) * 2;
            *(float2*)p = make_float2(v[2 * j] * inv, v[2 * j + 1] * inv);
        }
    }
}

// ---------------------------------------------------------------------------
// Two-half pipeline across two captured streams:
//   stream0: S_A -> (eA) -> G1_A -> sm_A -> G2_A -> (wait eJ) -> G2_B
//   s1:      (wait eA) -> S_B -> G1_B -> sm_B -> (eJ)
// S_B (memory-bound) overlaps G1_A (compute-bound); G2_A overlaps G1_B.
extern "C" void kernel_launch(void* const* d_in, const int* in_sizes, int n_in,
                              void* d_out, int out_size)
{
    const float* x_training = (const float*)d_in[0];  // KV
    const float* x_pre      = (const float*)d_in[1];  // Q
    float* out = (float*)d_out;

    cudaFuncSetAttribute(gemm1_kernel, cudaFuncAttributeMaxDynamicSharedMemorySize, SMEM1_SZ);
    cudaFuncSetAttribute(gemm2_kernel, cudaFuncAttributeMaxDynamicSharedMemorySize, SMEM2_SZ);

    __half *qh, *ql, *kh, *kl;
    cudaGetSymbolAddress((void**)&qh, g_qh);
    cudaGetSymbolAddress((void**)&ql, g_ql);
    cudaGetSymbolAddress((void**)&kh, g_kh);
    cudaGetSymbolAddress((void**)&kl, g_kl);

    cudaStream_t s1;
    cudaEvent_t eA, eJ;
    cudaStreamCreateWithFlags(&s1, cudaStreamNonBlocking);
    cudaEventCreateWithFlags(&eA, cudaEventDisableTiming);
    cudaEventCreateWithFlags(&eJ, cudaEventDisableTiming);

    const int nvecH = HB_ * C_ * N_ / 4;   // float4s per half per tensor

    // ---- half A on stream0 ----
    split_all_kernel<<<dim3(nvecH / 256, 2), 256>>>(x_pre, x_training, 0);
    cudaEventRecord(eA, 0);
    gemm1_kernel<<<dim3(C_ / 128, C_ / 128, HB_), 256, SMEM1_SZ>>>(qh, ql, kh, kl, 0);
    softmax512_split_kernel<<<HB_ * C_, 128>>>(0);
    gemm2_kernel<<<dim3(N_ / 128, C_ / 128, HB_), 256, SMEM2_SZ>>>(kh, out, 0);

    // ---- half B on s1 (forked after S_A so S_B overlaps G1_A) ----
    cudaStreamWaitEvent(s1, eA, 0);
    split_all_kernel<<<dim3(nvecH / 256, 2), 256, 0, s1>>>(x_pre, x_training, HB_);
    gemm1_kernel<<<dim3(C_ / 128, C_ / 128, HB_), 256, SMEM1_SZ, s1>>>(qh, ql, kh, kl, HB_);
    softmax512_split_kernel<<<HB_ * C_, 128, 0, s1>>>(HB_ * C_);
    cudaEventRecord(eJ, s1);

    // ---- join: G2_B on stream0 ----
    cudaStreamWaitEvent(0, eJ, 0);
    gemm2_kernel<<<dim3(N_ / 128, C_ / 128, HB_), 256, SMEM2_SZ>>>(kh, out, HB_);
}